// round 17
// baseline (speedup 1.0000x reference)
#include <cuda_runtime.h>
#include <cuda_bf16.h>
#include <cuda_fp16.h>
#include <cstdint>
#include <math.h>

#define NB 4
#define NS 2048
#define NHID 1024
#define NHEADS 16
#define DHEAD 64
#define MTOT (NB * NS)   // 8192

// ---------------------------------------------------------------------------
// Global scratch
// ---------------------------------------------------------------------------
__device__ __half g_x16[MTOT * NHID];               // X fp16
__device__ __half g_w16[3 * NHID * NHID];           // Wq|Wk|Wv fp16
__device__ __half g_wo16[NHID * NHID];              // Wo fp16
__device__ __half g_q16[NB * NHEADS * NS * DHEAD];  // Q fp16 (pre-scaled)
__device__ __half g_k16[NB * NHEADS * NS * DHEAD];  // K fp16
__device__ __half g_v16[NB * NHEADS * NS * DHEAD];  // V fp16
__device__ __half g_a16[MTOT * NHID];               // attn out fp16

// ===========================================================================
// Helpers
// ===========================================================================
__device__ __forceinline__ uint32_t smem_to_u32(const void* p) {
    uint32_t a;
    asm("{ .reg .u64 t; cvta.to.shared.u64 t, %1; cvt.u32.u64 %0, t; }"
        : "=r"(a) : "l"(p));
    return a;
}
__device__ __forceinline__ void cp_async16(uint32_t s, const void* g) {
    asm volatile("cp.async.cg.shared.global [%0], [%1], 16;" :: "r"(s), "l"(g));
}
__device__ __forceinline__ void cp_commit() {
    asm volatile("cp.async.commit_group;" ::: "memory");
}
template <int N>
__device__ __forceinline__ void cp_wait() {
    asm volatile("cp.async.wait_group %0;" :: "n"(N) : "memory");
}
__device__ __forceinline__ void ldmatrix_x4(uint32_t& d0, uint32_t& d1,
                                            uint32_t& d2, uint32_t& d3,
                                            uint32_t addr) {
    asm volatile("ldmatrix.sync.aligned.m8n8.x4.shared.b16 {%0,%1,%2,%3}, [%4];"
        : "=r"(d0), "=r"(d1), "=r"(d2), "=r"(d3) : "r"(addr));
}
__device__ __forceinline__ void ldmatrix_x4_trans(uint32_t& d0, uint32_t& d1,
                                                  uint32_t& d2, uint32_t& d3,
                                                  uint32_t addr) {
    asm volatile("ldmatrix.sync.aligned.m8n8.x4.trans.shared.b16 {%0,%1,%2,%3}, [%4];"
        : "=r"(d0), "=r"(d1), "=r"(d2), "=r"(d3) : "r"(addr));
}
__device__ __forceinline__ void mma_f16(float* c, const uint32_t* a,
                                        const uint32_t* b) {
    asm volatile(
        "mma.sync.aligned.m16n8k16.row.col.f32.f16.f16.f32 "
        "{%0,%1,%2,%3}, {%4,%5,%6,%7}, {%8,%9}, {%0,%1,%2,%3};"
        : "+f"(c[0]), "+f"(c[1]), "+f"(c[2]), "+f"(c[3])
        : "r"(a[0]), "r"(a[1]), "r"(a[2]), "r"(a[3]), "r"(b[0]), "r"(b[1]));
}
__device__ __forceinline__ uint32_t f2h2(float x, float y) {
    uint32_t r;
    asm("cvt.rn.f16x2.f32 %0, %1, %2;" : "=r"(r) : "f"(y), "f"(x));
    return r;
}
__device__ __forceinline__ float ex2f(float x) {
    float r;
    asm("ex2.approx.f32 %0, %1;" : "=f"(r) : "f"(x));
    return r;
}
__device__ __forceinline__ uint32_t ex2h2(uint32_t x) {
    uint32_t r;
    asm("ex2.approx.f16x2 %0, %1;" : "=r"(r) : "r"(x));
    return r;
}

#define L2E 1.4426950408889634f

// ===========================================================================
// Fused conversion: one launch converts X, Wq, Wk, Wv, Wo to fp16
// ===========================================================================
#define N4X (MTOT * NHID / 4)     // 2097152
#define N4W (NHID * NHID / 4)     // 262144

__global__ __launch_bounds__(256)
void cvt_all_kernel(const float* __restrict__ X,
                    const float* __restrict__ Wq,
                    const float* __restrict__ Wk,
                    const float* __restrict__ Wv,
                    const float* __restrict__ Wo)
{
    int i = blockIdx.x * 256 + threadIdx.x;
    const float* src;
    __half* dst;
    int off;
    if (i < N4X)                { src = X;  dst = g_x16;               off = i; }
    else if (i < N4X + N4W)     { src = Wq; dst = g_w16;               off = i - N4X; }
    else if (i < N4X + 2*N4W)   { src = Wk; dst = g_w16 + NHID*NHID;   off = i - N4X - N4W; }
    else if (i < N4X + 3*N4W)   { src = Wv; dst = g_w16 + 2*NHID*NHID; off = i - N4X - 2*N4W; }
    else                        { src = Wo; dst = g_wo16;              off = i - N4X - 3*N4W; }
    float4 v = ((const float4*)src)[off];
    uint2 o;
    o.x = f2h2(v.x, v.y);
    o.y = f2h2(v.z, v.w);
    ((uint2*)dst)[off] = o;
}

// ===========================================================================
// fp16 1-term GEMM: D = A * B.  CTA 128x256, warp 64x64, BK=32, 3 stages.
// qkvMode=1: scatter Q (fp16, pre-scaled 0.125*log2e), K, V into [B,NH,S,HD].
// qkvMode=0: fp32 out to Cf.
// ===========================================================================
#define GLDS 40
#define GA_BUF 10240
#define GB_BUF 20480
#define G1STAGE (GA_BUF + GB_BUF)          // 30720
#define GEMM_SMEM (3 * G1STAGE)            // 92160

__global__ __launch_bounds__(256, 1)
void gemm_1t_kernel(const __half* __restrict__ A,
                    const __half* __restrict__ B,
                    float* __restrict__ Cf, int qkvMode)
{
    extern __shared__ char smc[];
    const uint32_t sb = smem_to_u32(smc);

    const int t    = threadIdx.x;
    const int lane = t & 31;
    const int wid  = t >> 5;
    const int wm   = wid & 1;
    const int wn   = wid >> 1;
    const int m0   = blockIdx.y << 7;
    const int n0   = blockIdx.x << 8;

    const int rA = lane & 15;
    const int cA = (lane >> 4) << 3;
    const int rB = (lane & 7) + ((lane >> 4) << 3);
    const int cB = lane & 8;

    auto issue = [&](int c, int stg) {
        const int k0 = c << 5;
        const uint32_t st = sb + stg * G1STAGE;
#pragma unroll
        for (int j = 0; j < 2; j++) {
            int idx = t + (j << 8);
            int row = idx >> 2, ch = idx & 3;
            uint32_t so = (uint32_t)(row * 80 + ch * 16);
            cp_async16(st + so, A + (size_t)(m0 + row) * NHID + k0 + ch * 8);
        }
#pragma unroll
        for (int j = 0; j < 4; j++) {
            int idx = t + (j << 8);
            int row = idx >> 2, ch = idx & 3;
            uint32_t so = (uint32_t)(row * 80 + ch * 16);
            cp_async16(st + GA_BUF + so, B + (size_t)(n0 + row) * NHID + k0 + ch * 8);
        }
        cp_commit();
    };

    float acc[4][8][4];
#pragma unroll
    for (int mf = 0; mf < 4; mf++)
#pragma unroll
        for (int nf = 0; nf < 8; nf++)
#pragma unroll
            for (int r = 0; r < 4; r++) acc[mf][nf][r] = 0.f;

    issue(0, 0);
    issue(1, 1);

    for (int c = 0; c < 32; ++c) {
        if (c < 31) cp_wait<1>(); else cp_wait<0>();
        __syncthreads();
        if (c + 2 < 32) issue(c + 2, (c + 2) % 3);

        const uint32_t st = sb + (c % 3) * G1STAGE;
#pragma unroll
        for (int ks = 0; ks < 2; ks++) {
            const int k0 = ks << 4;
            uint32_t a[4][4];
#pragma unroll
            for (int mf = 0; mf < 4; mf++) {
                uint32_t ro = (uint32_t)((wm * 64 + mf * 16 + rA) * GLDS + k0 + cA) * 2;
                ldmatrix_x4(a[mf][0], a[mf][1], a[mf][2], a[mf][3], st + ro);
            }
#pragma unroll
            for (int p = 0; p < 4; p++) {
                uint32_t ro = (uint32_t)((wn * 64 + p * 16 + rB) * GLDS + k0 + cB) * 2;
                uint32_t h0, h1, h2, h3;
                ldmatrix_x4(h0, h1, h2, h3, st + GA_BUF + ro);
                uint32_t b0[2] = {h0, h1}, b1[2] = {h2, h3};
#pragma unroll
                for (int mf = 0; mf < 4; mf++) {
                    mma_f16(acc[mf][2 * p],     a[mf], b0);
                    mma_f16(acc[mf][2 * p + 1], a[mf], b1);
                }
            }
        }
    }

    const int rowBase = m0 + wm * 64 + (lane >> 2);
    const int colBase = n0 + wn * 64 + ((lane & 3) << 1);

    if (qkvMode) {
        const int which = n0 >> 10;
        const float sc = (which == 0) ? 0.125f * L2E : 1.0f;
        __half* dst = (which == 0) ? g_q16 : (which == 1) ? g_k16 : g_v16;
#pragma unroll
        for (int mf = 0; mf < 4; mf++)
#pragma unroll
            for (int nf = 0; nf < 8; nf++) {
                int n = colBase + nf * 8;
                int r = n & 1023;
                int h = r >> 6, d = r & 63;
#pragma unroll
                for (int half = 0; half < 2; half++) {
                    int m = rowBase + mf * 16 + half * 8;
                    int b = m >> 11, s = m & (NS - 1);
                    size_t idx = ((((size_t)(b * NHEADS + h)) * NS + s) << 6) + d;
                    *(uint32_t*)(dst + idx) =
                        f2h2(acc[mf][nf][half * 2] * sc,
                             acc[mf][nf][half * 2 + 1] * sc);
                }
            }
    } else {
#pragma unroll
        for (int mf = 0; mf < 4; mf++)
#pragma unroll
            for (int nf = 0; nf < 8; nf++) {
                int n = colBase + nf * 8;
#pragma unroll
                for (int half = 0; half < 2; half++) {
                    int m = rowBase + mf * 16 + half * 8;
                    *(float2*)(Cf + (size_t)m * NHID + n) =
                        make_float2(acc[mf][nf][half * 2], acc[mf][nf][half * 2 + 1]);
                }
            }
    }
}

// ===========================================================================
// Flash attention: Q/K/V fp16 1-term; Q fragments cached in registers;
// log2 softmax, ex2.f16x2, l via ones-MMA.
// 3-stage KV cp.async pipeline with wait_group<1> (2 compute-phases of slack).
// CTA = (b,h) x 128 q-rows, 8 warps, K-tile 128.
// ===========================================================================
#define KT 128
#define ALDS 72
#define ABUF (128 * 144)           // 18432
#define ASTG (2 * ABUF)            // K, V = 36864
#define OQ 0
#define OST ABUF                   // 18432
#define OMSK (OST + 3 * ASTG)      // 129024  (3 stages)
#define ATTN_SMEM (OMSK + 2048)

__global__ __launch_bounds__(256, 1)
void attn_tc_kernel(const float* __restrict__ mask)
{
    extern __shared__ char smc[];
    const uint32_t sb = smem_to_u32(smc);

    const int t    = threadIdx.x;
    const int lane = t & 31;
    const int w    = t >> 5;

    const int bh = blockIdx.y;
    const int b  = bh >> 4;
    const int h  = bh & 15;
    const int q0 = blockIdx.x << 7;

    const int rA = lane & 15;
    const int cA = (lane >> 4) << 3;
    const int rB = (lane & 7) + ((lane >> 4) << 3);
    const int cB = lane & 8;
    const int c0 = (lane & 3) << 1;

    const size_t qbase  = ((size_t)bh * NS + q0) * DHEAD;
    const size_t kvbase = (size_t)bh * NS * DHEAD;

    auto issue_kv = [&](int kt, int stg) {
        const size_t base = kvbase + (size_t)kt * KT * DHEAD;
        const uint32_t st = sb + OST + stg * ASTG;
#pragma unroll
        for (int j = 0; j < 4; j++) {
            int idx = t + (j << 8);
            int row = idx >> 3, ch = idx & 7;
            uint32_t so = (uint32_t)(row * 144 + ch * 16);
            size_t go = base + row * DHEAD + ch * 8;
            cp_async16(st + so, g_k16 + go);
            cp_async16(st + ABUF + so, g_v16 + go);
        }
        if (t < 32)
            cp_async16(sb + OMSK + stg * 512 + t * 16,
                       mask + (size_t)b * NS + kt * KT + t * 4);
        cp_commit();
    };

    // prologue: group0 = Q + KV0, group1 = KV1
#pragma unroll
    for (int j = 0; j < 4; j++) {
        int idx = t + (j << 8);
        int row = idx >> 3, ch = idx & 7;
        uint32_t so = (uint32_t)(row * 144 + ch * 16);
        cp_async16(sb + OQ + so, g_q16 + qbase + row * DHEAD + ch * 8);
    }
    issue_kv(0, 0);           // commits group 0 (Q + KV0)
    issue_kv(1, 1);           // group 1 (KV1)

    // wait for group 0 (Q + KV0); KV1 may still be in flight
    cp_wait<1>();
    __syncthreads();
    uint32_t aqr[4][4];
#pragma unroll
    for (int ks = 0; ks < 4; ks++) {
        uint32_t qo = (uint32_t)((w * 16 + rA) * ALDS + ks * 16 + cA) * 2;
        ldmatrix_x4(aqr[ks][0], aqr[ks][1], aqr[ks][2], aqr[ks][3], sb + OQ + qo);
    }

    float accs[16][4];
    uint32_t pp[16][2];
    float acco[8][4];
    float acco_l[4] = {0.f, 0.f, 0.f, 0.f};
    float m0 = -INFINITY, m1 = -INFINITY;
#pragma unroll
    for (int nf = 0; nf < 8; nf++)
#pragma unroll
        for (int r = 0; r < 4; r++) acco[nf][r] = 0.f;

    const uint32_t bones[2] = {0x3C003C00u, 0x3C003C00u};

    for (int kt = 0; kt < NS / KT; kt++) {
        if (kt > 0) {
            if (kt < NS / KT - 1) cp_wait<1>(); else cp_wait<0>();
            __syncthreads();
        }
        if (kt + 2 < NS / KT) issue_kv(kt + 2, (kt + 2) % 3);

        const int stg = kt % 3;
        const uint32_t st = sb + OST + stg * ASTG;
        const float* msk = (const float*)(smc + OMSK + stg * 512);

        // ---- S = Q K^T (Q from registers) ----
#pragma unroll
        for (int nf = 0; nf < 16; nf++)
#pragma unroll
            for (int r = 0; r < 4; r++) accs[nf][r] = 0.f;

#pragma unroll
        for (int ks = 0; ks < 4; ks++) {
#pragma unroll
            for (int p = 0; p < 8; p++) {
                uint32_t ko = (uint32_t)((p * 16 + rB) * ALDS + ks * 16 + cB) * 2;
                uint32_t h0, h1, h2, h3;
                ldmatrix_x4(h0, h1, h2, h3, st + ko);
                uint32_t bk0[2] = {h0, h1}, bk1[2] = {h2, h3};
                mma_f16(accs[2 * p],     aqr[ks], bk0);
                mma_f16(accs[2 * p + 1], aqr[ks], bk1);
            }
        }

        // ---- + mask*log2e ----
#pragma unroll
        for (int nf = 0; nf < 16; nf++) {
            float mk0 = msk[nf * 8 + c0];
            float mk1 = msk[nf * 8 + c0 + 1];
            accs[nf][0] = fmaf(mk0, L2E, accs[nf][0]);
            accs[nf][1] = fmaf(mk1, L2E, accs[nf][1]);
            accs[nf][2] = fmaf(mk0, L2E, accs[nf][2]);
            accs[nf][3] = fmaf(mk1, L2E, accs[nf][3]);
        }

        // ---- online softmax (log2 domain) ----
        float tm0 = -INFINITY, tm1 = -INFINITY;
#pragma unroll
        for (int nf = 0; nf < 16; nf++) {
            tm0 = fmaxf(tm0, fmaxf(accs[nf][0], accs[nf][1]));
            tm1 = fmaxf(tm1, fmaxf(accs[nf][2], accs[nf][3]));
        }
        tm0 = fmaxf(tm0, __shfl_xor_sync(0xffffffffu, tm0, 1));
        tm0 = fmaxf(tm0, __shfl_xor_sync(0xffffffffu, tm0, 2));
        tm1 = fmaxf(tm1, __shfl_xor_sync(0xffffffffu, tm1, 1));
        tm1 = fmaxf(tm1, __shfl_xor_sync(0xffffffffu, tm1, 2));

        float mn0 = fmaxf(m0, tm0), mn1 = fmaxf(m1, tm1);
        float cr0 = ex2f(m0 - mn0), cr1 = ex2f(m1 - mn1);
        m0 = mn0; m1 = mn1;

        // ---- P = 2^(S-m) via packed fp16x2 exp ----
#pragma unroll
        for (int nf = 0; nf < 16; nf++) {
            pp[nf][0] = ex2h2(f2h2(accs[nf][0] - mn0, accs[nf][1] - mn0));
            pp[nf][1] = ex2h2(f2h2(accs[nf][2] - mn1, accs[nf][3] - mn1));
        }

#pragma unroll
        for (int nf = 0; nf < 8; nf++) {
            acco[nf][0] *= cr0; acco[nf][1] *= cr0;
            acco[nf][2] *= cr1; acco[nf][3] *= cr1;
        }
        acco_l[0] *= cr0;
        acco_l[2] *= cr1;

        // ---- O += P V ----
#pragma unroll
        for (int kc = 0; kc < 8; kc++) {
            uint32_t aph[4] = { pp[2 * kc][0], pp[2 * kc][1],
                                pp[2 * kc + 1][0], pp[2 * kc + 1][1] };
            mma_f16(acco_l, aph, bones);
#pragma unroll
            for (int pv = 0; pv < 4; pv++) {
                uint32_t vo = (uint32_t)((kc * 16 + rA) * ALDS + pv * 16 + cA) * 2;
                uint32_t h0, h1, h2, h3;
                ldmatrix_x4_trans(h0, h1, h2, h3, st + ABUF + vo);
                uint32_t bv0[2] = {h0, h1}, bv1[2] = {h2, h3};
                mma_f16(acco[2 * pv],     aph, bv0);
                mma_f16(acco[2 * pv + 1], aph, bv1);
            }
        }
    }

    // ---- epilogue: single-fp16 output ----
    float inv0 = 1.f / acco_l[0];
    float inv1 = 1.f / acco_l[2];
    int row0 = q0 + w * 16 + (lane >> 2);
#pragma unroll
    for (int nf = 0; nf < 8; nf++) {
        int d = nf * 8 + c0;
        size_t i0 = ((size_t)(b * NS) + row0) * NHID + h * DHEAD + d;
        size_t i1 = i0 + (size_t)8 * NHID;
        *(uint32_t*)(g_a16 + i0) = f2h2(acco[nf][0] * inv0, acco[nf][1] * inv0);
        *(uint32_t*)(g_a16 + i1) = f2h2(acco[nf][2] * inv1, acco[nf][3] * inv1);
    }
}

// ---------------------------------------------------------------------------
// Launch
// ---------------------------------------------------------------------------
extern "C" void kernel_launch(void* const* d_in, const int* in_sizes, int n_in,
                              void* d_out, int out_size)
{
    const float* X    = (const float*)d_in[0];
    const float* mask = (const float*)d_in[1];
    const float* Wq   = (const float*)d_in[2];
    const float* Wk   = (const float*)d_in[3];
    const float* Wv   = (const float*)d_in[4];
    const float* Wo   = (const float*)d_in[5];
    float* out = (float*)d_out;

    __half *x16, *w16, *wo16, *a16;
    cudaGetSymbolAddress((void**)&x16,  g_x16);
    cudaGetSymbolAddress((void**)&w16,  g_w16);
    cudaGetSymbolAddress((void**)&wo16, g_wo16);
    cudaGetSymbolAddress((void**)&a16,  g_a16);

    cudaFuncSetAttribute(gemm_1t_kernel,
                         cudaFuncAttributeMaxDynamicSharedMemorySize, GEMM_SMEM);
    cudaFuncSetAttribute(attn_tc_kernel,
                         cudaFuncAttributeMaxDynamicSharedMemorySize, ATTN_SMEM);

    // fused conversions (1 launch)
    int n4tot = N4X + 4 * N4W;
    cvt_all_kernel<<<n4tot / 256, 256>>>(X, Wq, Wk, Wv, Wo);

    // fused QKV GEMM (1-term)
    dim3 gq(3 * NHID / 256, MTOT / 128);   // 12 x 64
    gemm_1t_kernel<<<gq, 256, GEMM_SMEM>>>(x16, w16, nullptr, 1);

    // attention
    dim3 ga(NS / KT, NB * NHEADS);         // 16 x 64
    attn_tc_kernel<<<ga, 256, ATTN_SMEM>>>(mask);

    // output projection (1-term)
    dim3 go(NHID / 256, MTOT / 128);       // 4 x 64
    gemm_1t_kernel<<<go, 256, GEMM_SMEM>>>(a16, wo16, out, 0);
}